// round 9
// baseline (speedup 1.0000x reference)
#include <cuda_runtime.h>
#include <math.h>
#include <stdint.h>

// Problem constants
#define Bn   32
#define NIc  2048
#define NOc  128
#define TIc  32              // i's per block in pass kernels
#define NTc  (NIc / TIc)     // 64 tiles
#define RW   36              // g_part row: [0]=S0, [4..19]=S1(permuted), [20..35]=S2(permuted)
#define EPSf 1e-9f
#define LOG2PIf 1.8378770664093453f

#define LAM1 0.0005f
#define LAM2 0.000975f
#define LAM3 0.00142625f

// Module-static scratch (allocation-free, deterministic)
__device__ __align__(16) float g_part[(size_t)Bn * NTc * NOc * RW];     // 37.7 MB
// g_statsT[b][s][j]: s 0..15 = A(d)=1/sig, 16..31 = B(d)=-2mu/sig, 32 = L'
__device__ __align__(16) float g_statsT[(size_t)Bn * 33 * NOc];
__device__ __align__(16) float g_x[(size_t)Bn * NIc * NOc];             // logits, 33.5 MB
__device__ __align__(16) float2 g_rowMT[(size_t)Bn * NIc];              // (M, a/T) per row
// Transposed+packed W: [i][k2][j] -> ulonglong2 = slots (2*k2, 2*k2+1)
// slot k=pp*4+r holds (W[i][j][2pp][r], W[i][j][2pp+1][r])
__device__ __align__(16) ulonglong2 g_Wt[(size_t)NIc * 4 * NOc];        // 16.8 MB

// ---------------- f32x2 packed helpers ----------------
static __device__ __forceinline__ uint64_t pk2(float lo, float hi) {
    uint64_t r; asm("mov.b64 %0, {%1, %2};" : "=l"(r) : "f"(lo), "f"(hi)); return r;
}
static __device__ __forceinline__ void upk2(uint64_t v, float& lo, float& hi) {
    asm("mov.b64 {%0, %1}, %2;" : "=f"(lo), "=f"(hi) : "l"(v));
}
static __device__ __forceinline__ uint64_t fma2(uint64_t a, uint64_t b, uint64_t c) {
    uint64_t d; asm("fma.rn.f32x2 %0, %1, %2, %3;" : "=l"(d) : "l"(a), "l"(b), "l"(c)); return d;
}
static __device__ __forceinline__ uint64_t mul2(uint64_t a, uint64_t b) {
    uint64_t d; asm("mul.rn.f32x2 %0, %1, %2;" : "=l"(d) : "l"(a), "l"(b)); return d;
}
static __device__ __forceinline__ uint64_t add2(uint64_t a, uint64_t b) {
    uint64_t d; asm("add.rn.f32x2 %0, %1, %2;" : "=l"(d) : "l"(a), "l"(b)); return d;
}

// Coalesced packed-W load: 4x LDG.128 (nL=4); both h-threads of a j hit the
// same addresses (warp-level broadcast).
static __device__ __forceinline__ void loadWt8(int i, int j, uint64_t* wpk) {
    const ulonglong2* wt = g_Wt + (size_t)i * 4 * NOc + j;
    const ulonglong2 a = wt[0], b = wt[NOc], c = wt[2 * NOc], d = wt[3 * NOc];
    wpk[0] = a.x; wpk[1] = a.y; wpk[2] = b.x; wpk[3] = b.y;
    wpk[4] = c.x; wpk[5] = c.y; wpk[6] = d.x; wpk[7] = d.y;
}

// votes for this thread's 4 slots: kk = pp*2+qq, q = q0+qq, slot k = pp*4+q,
// value = (v[8pp+q], v[8pp+q+4]); pd[4r+q] = dup-packed pose.
static __device__ __forceinline__ void votes4(const uint64_t* __restrict__ wpk,
                                              const uint64_t* __restrict__ pd,
                                              int q0, uint64_t* __restrict__ vp) {
    #pragma unroll
    for (int kk = 0; kk < 4; kk++) {
        const int pp = kk >> 1, q = q0 + (kk & 1);
        uint64_t a = mul2(wpk[pp * 4 + 0], pd[0 + q]);
        a = fma2(wpk[pp * 4 + 1], pd[4 + q], a);
        a = fma2(wpk[pp * 4 + 2], pd[8 + q], a);
        vp[kk] = fma2(wpk[pp * 4 + 3], pd[12 + q], a);
    }
}

// ============================================================================
// W transpose+pack kernel (once per launch). Block=128 (j=tid), grid=NIc.
// ============================================================================
__global__ __launch_bounds__(128) void wt_kernel(const float* __restrict__ W) {
    const int i = blockIdx.x;
    const int j = threadIdx.x;
    const float4* wr = (const float4*)(W + ((size_t)i * NOc + j) * 16);
    const float4 w0 = wr[0], w1 = wr[1], w2 = wr[2], w3 = wr[3];
    ulonglong2* out = g_Wt + (size_t)i * 4 * NOc + j;
    out[0]        = make_ulonglong2(pk2(w0.x, w1.x), pk2(w0.y, w1.y));
    out[NOc]      = make_ulonglong2(pk2(w0.z, w1.z), pk2(w0.w, w1.w));
    out[2 * NOc]  = make_ulonglong2(pk2(w2.x, w3.x), pk2(w2.y, w3.y));
    out[3 * NOc]  = make_ulonglong2(pk2(w2.z, w3.z), pk2(w2.w, w3.w));
}

// ============================================================================
// K1: logit kernel. Block = 256 threads: thread owns (j = t>>1, q-half
// h = t&1 -> q in {2h, 2h+1}), both b's. x = L' - 0.5*sum(A*v^2 + B*v);
// halves combined with one shfl. Barrier-free loop.
// ============================================================================
__global__ __launch_bounds__(256, 3) void logit_kernel(const float* __restrict__ pose)
{
    __shared__ uint64_t sPoseD[2][TIc][16];

    const int t    = threadIdx.x;
    const int j    = t >> 1;
    const int h    = t & 1;
    const int q0   = h << 1;
    const int tile = blockIdx.x;
    const int b0   = blockIdx.y << 1;
    const int i0   = tile * TIc;

    for (int idx = t; idx < 2 * TIc * 16; idx += 256) {
        const int bb = idx >> 9, rem = idx & 511;   // TIc*16 = 512
        const float f = pose[((size_t)(b0 + bb) * NIc + i0 + (rem >> 4)) * 16 + (rem & 15)];
        sPoseD[bb][rem >> 4][rem & 15] = pk2(f, f);
    }

    // per-thread A/B for 4 slots x 2 b's
    uint64_t Apk[2][4], Bpk[2][4];
    float sL[2];
    #pragma unroll
    for (int bb = 0; bb < 2; bb++) {
        const float* st = g_statsT + (size_t)(b0 + bb) * 33 * NOc;
        #pragma unroll
        for (int kk = 0; kk < 4; kk++) {
            const int pp = kk >> 1, q = q0 + (kk & 1);
            const int dlo = 8 * pp + q, dhi = dlo + 4;
            Apk[bb][kk] = pk2(st[dlo * NOc + j], st[dhi * NOc + j]);
            Bpk[bb][kk] = pk2(st[(16 + dlo) * NOc + j], st[(16 + dhi) * NOc + j]);
        }
        sL[bb] = st[32 * NOc + j];
    }
    __syncthreads();

    #pragma unroll 2
    for (int ii = 0; ii < TIc; ii++) {
        uint64_t wpk[8];
        loadWt8(i0 + ii, j, wpk);
        #pragma unroll
        for (int bb = 0; bb < 2; bb++) {
            uint64_t vp[4];
            votes4(wpk, sPoseD[bb][ii], q0, vp);
            uint64_t q2a = 0ull, q2b = 0ull;
            #pragma unroll
            for (int kk = 0; kk < 4; kk += 2) {
                const uint64_t t0 = fma2(Apk[bb][kk],     vp[kk],     Bpk[bb][kk]);
                const uint64_t t1 = fma2(Apk[bb][kk + 1], vp[kk + 1], Bpk[bb][kk + 1]);
                q2a = fma2(t0, vp[kk],     q2a);
                q2b = fma2(t1, vp[kk + 1], q2b);
            }
            float ql, qh; upk2(add2(q2a, q2b), ql, qh);
            float qs = ql + qh;
            qs += __shfl_xor_sync(0xffffffffu, qs, 1);   // combine q-halves
            if (!h)
                g_x[((size_t)(b0 + bb) * NIc + i0 + ii) * NOc + j] = fmaf(-0.5f, qs, sL[bb]);
        }
    }
}

// ============================================================================
// K2: row softmax stats. Warp per (b,i) row: writes (M, act/T).
// ============================================================================
__global__ __launch_bounds__(256) void rowmt_kernel(const float* __restrict__ act)
{
    const int row  = (blockIdx.x << 3) + (threadIdx.x >> 5);
    const int lane = threadIdx.x & 31;
    const float* xr = g_x + (size_t)row * NOc;

    const float x0 = xr[lane], x1 = xr[lane + 32], x2 = xr[lane + 64], x3 = xr[lane + 96];
    float m = fmaxf(fmaxf(x0, x1), fmaxf(x2, x3));
    #pragma unroll
    for (int off = 16; off; off >>= 1)
        m = fmaxf(m, __shfl_xor_sync(0xffffffffu, m, off));
    float s = __expf(x0 - m) + __expf(x1 - m) + __expf(x2 - m) + __expf(x3 - m);
    #pragma unroll
    for (int off = 16; off; off >>= 1)
        s += __shfl_xor_sync(0xffffffffu, s, off);
    if (lane == 0)
        g_rowMT[row] = make_float2(m, __fdividef(act[row], s));
}

// ============================================================================
// K3 / uniform pass: accumulate S0/S1/S2 partials. Same split-d layout as K1.
// Barrier-free loop.
// ============================================================================
template <bool UNIFORM>
__global__ __launch_bounds__(256, 3) void accum_kernel(
    const float* __restrict__ pose, const float* __restrict__ act)
{
    __shared__ uint64_t sPoseD[2][TIc][16];
    __shared__ float    sAct[2][TIc];
    __shared__ float2   sMT[2][TIc];

    const int t    = threadIdx.x;
    const int j    = t >> 1;
    const int h    = t & 1;
    const int q0   = h << 1;
    const int tile = blockIdx.x;
    const int b0   = blockIdx.y << 1;
    const int i0   = tile * TIc;

    for (int idx = t; idx < 2 * TIc * 16; idx += 256) {
        const int bb = idx >> 9, rem = idx & 511;
        const float f = pose[((size_t)(b0 + bb) * NIc + i0 + (rem >> 4)) * 16 + (rem & 15)];
        sPoseD[bb][rem >> 4][rem & 15] = pk2(f, f);
    }
    if (t < 2 * TIc) {
        const int bb = t >> 5, ii = t & 31;   // TIc = 32
        if (UNIFORM) sAct[bb][ii] = act[(b0 + bb) * NIc + i0 + ii];
        else         sMT[bb][ii]  = g_rowMT[(size_t)(b0 + bb) * NIc + i0 + ii];
    }
    __syncthreads();

    uint64_t S1[2][4], S2[2][4];
    float S0[2] = {0.f, 0.f};
    #pragma unroll
    for (int bb = 0; bb < 2; bb++)
        #pragma unroll
        for (int kk = 0; kk < 4; kk++) { S1[bb][kk] = 0ull; S2[bb][kk] = 0ull; }

    #pragma unroll 2
    for (int ii = 0; ii < TIc; ii++) {
        uint64_t wpk[8];
        loadWt8(i0 + ii, j, wpk);

        float xv[2];
        if (!UNIFORM) {
            #pragma unroll
            for (int bb = 0; bb < 2; bb++)
                xv[bb] = g_x[((size_t)(b0 + bb) * NIc + i0 + ii) * NOc + j];
        }

        #pragma unroll
        for (int bb = 0; bb < 2; bb++) {
            uint64_t vp[4];
            votes4(wpk, sPoseD[bb][ii], q0, vp);
            float rp;
            if (UNIFORM) {
                rp = sAct[bb][ii] * (1.f / NOc);
            } else {
                const float2 mt = sMT[bb][ii];
                rp = __expf(xv[bb] - mt.x) * mt.y;
            }
            if (!h) S0[bb] += rp;      // count each j once
            const uint64_t rpp = pk2(rp, rp);
            #pragma unroll
            for (int kk = 0; kk < 4; kk++) {
                const uint64_t tmp = mul2(rpp, vp[kk]);
                S1[bb][kk] = add2(S1[bb][kk], tmp);
                S2[bb][kk] = fma2(tmp, vp[kk], S2[bb][kk]);
            }
        }
    }

    #pragma unroll
    for (int bb = 0; bb < 2; bb++) {
        float* pb = g_part + ((size_t)((b0 + bb) * NTc + tile) * NOc + j) * RW;
        if (!h) pb[0] = S0[bb];
        #pragma unroll
        for (int kk = 0; kk < 4; kk++) {
            const int k = (kk >> 1) * 4 + q0 + (kk & 1);   // global slot 0..7
            *(uint64_t*)(pb + 4  + 2 * k) = S1[bb][kk];
            *(uint64_t*)(pb + 20 + 2 * k) = S2[bb][kk];
        }
    }
}

// ============================================================================
// Stats kernel: one warp per (b, j); lane = stat slot; coalesced tile loop.
// Emits A/B/L' for the next pass (or the final outputs).
// ============================================================================
template <bool FINAL>
__global__ __launch_bounds__(256) void stats_kernel(
    const float* __restrict__ beta_v,
    const float* __restrict__ beta_a,
    float lam,
    float* __restrict__ out)
{
    const int warp = (blockIdx.x * blockDim.x + threadIdx.x) >> 5;
    const int lane = threadIdx.x & 31;
    const int b = warp >> 7;
    const int j = warp & 127;

    const float* base = g_part + ((size_t)b * NTc * NOc + j) * RW;
    float acc = 0.f, acc2 = 0.f;
    #pragma unroll 4
    for (int tile = 0; tile < NTc; tile++) {
        const float* row = base + (size_t)tile * (NOc * RW);
        acc += row[lane];
        if (lane < 4) acc2 += row[32 + lane];
    }

    const int d  = lane & 15;
    const int q  = d & 3, pp = (d >> 3) & 1, hd = (d >> 2) & 1;
    const int sl = 8 * pp + 2 * q + hd;
    const float S0  = __shfl_sync(0xffffffffu, acc, 0);
    const float S1d = __shfl_sync(0xffffffffu, acc, 4 + sl);
    const float s2a = __shfl_sync(0xffffffffu, acc, (20 + sl) & 31);
    const float s2b = __shfl_sync(0xffffffffu, acc2, (sl >= 12) ? (sl - 12) : 0);
    const float S2d = (sl < 12) ? s2a : s2b;

    const float Rs = S0 + EPSf;
    const float invRs = 1.f / Rs;
    const float muv = S1d * invRs;
    const float srp = S2d - 2.f * muv * S1d + muv * muv * S0;  // exact expansion
    const float sig = srp * invRs + EPSf;
    const float A   = 1.f / sig;
    const float lg  = logf(sig);
    float logsum = lg;
    #pragma unroll
    for (int off = 8; off; off >>= 1)
        logsum += __shfl_xor_sync(0xffffffffu, logsum, off);
    float muq = muv * muv * A;          // for L' correction
    #pragma unroll
    for (int off = 8; off; off >>= 1)
        muq += __shfl_xor_sync(0xffffffffu, muq, off);

    const float cost = (16.f * beta_v[j] + 0.5f * logsum) * Rs;
    const float aout = 1.f / (1.f + expf(-(lam * (beta_a[j] - cost))));

    if (FINAL) {
        if (lane < 16) out[(size_t)(b * NOc + j) * 16 + d] = muv;
        if (lane == 0) out[(size_t)Bn * NOc * 16 + b * NOc + j] = aout;
    } else {
        float* st = g_statsT + (size_t)b * 33 * NOc;
        if (lane < 16) {
            st[d * NOc + j]        = A;                 // A = 1/sig
            st[(16 + d) * NOc + j] = -2.f * muv * A;    // B = -2mu/sig
        }
        if (lane == 0)
            st[32 * NOc + j] = logf(aout + EPSf) - 0.5f * logsum
                               - 8.f * LOG2PIf - 0.5f * muq;   // L'
    }
}

extern "C" void kernel_launch(void* const* d_in, const int* in_sizes, int n_in,
                              void* d_out, int out_size) {
    const float* pose   = (const float*)d_in[0];
    const float* act    = (const float*)d_in[1];
    const float* W      = (const float*)d_in[2];
    const float* beta_v = (const float*)d_in[3];
    const float* beta_a = (const float*)d_in[4];
    float* out = (float*)d_out;

    dim3 gp(NTc, Bn / 2);                       // 64 x 16 blocks of 256
    const int rgrid = (Bn * NIc) / 8;           // 8192 blocks of 256 (warp/row)
    const int sgrid = (Bn * NOc * 32) / 256;    // 512 blocks of 256

    wt_kernel<<<NIc, 128>>>(W);                 // pack+transpose W once

    // t=0: uniform R
    accum_kernel<true><<<gp, 256>>>(pose, act);
    stats_kernel<false><<<sgrid, 256>>>(beta_v, beta_a, LAM1, out);
    // t=1
    logit_kernel<<<gp, 256>>>(pose);
    rowmt_kernel<<<rgrid, 256>>>(act);
    accum_kernel<false><<<gp, 256>>>(pose, act);
    stats_kernel<false><<<sgrid, 256>>>(beta_v, beta_a, LAM2, out);
    // t=2
    logit_kernel<<<gp, 256>>>(pose);
    rowmt_kernel<<<rgrid, 256>>>(act);
    accum_kernel<false><<<gp, 256>>>(pose, act);
    stats_kernel<true><<<sgrid, 256>>>(beta_v, beta_a, LAM3, out);
}

// round 10
// speedup vs baseline: 1.1844x; 1.1844x over previous
#include <cuda_runtime.h>
#include <math.h>
#include <stdint.h>

// Problem constants
#define Bn   32
#define NIc  2048
#define NOc  128
#define TIc  32              // i's per block in pass kernels
#define NTc  (NIc / TIc)     // 64 tiles
#define RW   36              // g_part row: [0]=S0, [4..19]=S1(permuted), [20..35]=S2(permuted)
#define EPSf 1e-9f
#define LOG2PIf 1.8378770664093453f

#define LAM1 0.0005f
#define LAM2 0.000975f
#define LAM3 0.00142625f

// Module-static scratch (allocation-free, deterministic)
__device__ __align__(16) float g_part[(size_t)Bn * NTc * NOc * RW];     // 37.7 MB
// g_statsT[b][s][j]: s 0..15 = A(d)=1/sig, 16..31 = B(d)=-2mu/sig, 32 = L'
__device__ __align__(16) float g_statsT[(size_t)Bn * 33 * NOc];
__device__ __align__(16) float g_x[(size_t)Bn * NIc * NOc];             // logits, 33.5 MB
__device__ __align__(16) float2 g_rowMT[(size_t)Bn * NIc];              // (M, a/T) per row
// Transposed+packed W: [i][k2][j] -> ulonglong2 = slots (2*k2, 2*k2+1)
// slot k=pp*4+r holds (W[i][j][2pp][r], W[i][j][2pp+1][r])
__device__ __align__(16) ulonglong2 g_Wt[(size_t)NIc * 4 * NOc];        // 16.8 MB

// ---------------- f32x2 packed helpers ----------------
static __device__ __forceinline__ uint64_t pk2(float lo, float hi) {
    uint64_t r; asm("mov.b64 %0, {%1, %2};" : "=l"(r) : "f"(lo), "f"(hi)); return r;
}
static __device__ __forceinline__ void upk2(uint64_t v, float& lo, float& hi) {
    asm("mov.b64 {%0, %1}, %2;" : "=f"(lo), "=f"(hi) : "l"(v));
}
static __device__ __forceinline__ uint64_t fma2(uint64_t a, uint64_t b, uint64_t c) {
    uint64_t d; asm("fma.rn.f32x2 %0, %1, %2, %3;" : "=l"(d) : "l"(a), "l"(b), "l"(c)); return d;
}
static __device__ __forceinline__ uint64_t mul2(uint64_t a, uint64_t b) {
    uint64_t d; asm("mul.rn.f32x2 %0, %1, %2;" : "=l"(d) : "l"(a), "l"(b)); return d;
}
static __device__ __forceinline__ uint64_t add2(uint64_t a, uint64_t b) {
    uint64_t d; asm("add.rn.f32x2 %0, %1, %2;" : "=l"(d) : "l"(a), "l"(b)); return d;
}

// ---------------- cp.async helpers ----------------
static __device__ __forceinline__ void cpa16(uint32_t smem_dst, const void* gsrc) {
    asm volatile("cp.async.cg.shared.global [%0], [%1], 16;" :: "r"(smem_dst), "l"(gsrc));
}
static __device__ __forceinline__ void cpa_commit() {
    asm volatile("cp.async.commit_group;");
}
template <int N> static __device__ __forceinline__ void cpa_wait() {
    asm volatile("cp.async.wait_group %0;" :: "n"(N));
}

// votes: slot k=(pp*4+q) = (v[8pp+q], v[8pp+q+4]); wpk[pp*4+r]=(W[2pp][r],W[2pp+1][r]);
// pd[4r+q] = dup-packed pose (pose[r][q], pose[r][q])
static __device__ __forceinline__ void votes8(const uint64_t* __restrict__ wpk,
                                              const uint64_t* __restrict__ pd,
                                              uint64_t* __restrict__ vp) {
    #pragma unroll
    for (int k = 0; k < 8; k++) {
        const int pp = k >> 2, q = k & 3;
        uint64_t a = mul2(wpk[pp * 4 + 0], pd[0 + q]);
        a = fma2(wpk[pp * 4 + 1], pd[4 + q], a);
        a = fma2(wpk[pp * 4 + 2], pd[8 + q], a);
        vp[k] = fma2(wpk[pp * 4 + 3], pd[12 + q], a);
    }
}

// ============================================================================
// W transpose+pack kernel (once per launch). Block=128 (j=tid), grid=NIc.
// ============================================================================
__global__ __launch_bounds__(128) void wt_kernel(const float* __restrict__ W) {
    const int i = blockIdx.x;
    const int j = threadIdx.x;
    const float4* wr = (const float4*)(W + ((size_t)i * NOc + j) * 16);
    const float4 w0 = wr[0], w1 = wr[1], w2 = wr[2], w3 = wr[3];
    ulonglong2* out = g_Wt + (size_t)i * 4 * NOc + j;
    out[0]        = make_ulonglong2(pk2(w0.x, w1.x), pk2(w0.y, w1.y));
    out[NOc]      = make_ulonglong2(pk2(w0.z, w1.z), pk2(w0.w, w1.w));
    out[2 * NOc]  = make_ulonglong2(pk2(w2.x, w3.x), pk2(w2.y, w3.y));
    out[3 * NOc]  = make_ulonglong2(pk2(w2.z, w3.z), pk2(w2.w, w3.w));
}

// Per-thread W prefetch: thread j stages ITS OWN 4x16B chunks of tile i into
// buffer buf. No cross-thread deps -> no barrier needed, wait_group only.
static __device__ __forceinline__ void prefetchW(uint32_t sWaddr, int buf, int i, int j) {
    const ulonglong2* src = g_Wt + (size_t)i * 4 * NOc + j;
    const uint32_t dst = sWaddr + (uint32_t)buf * 8192 + (uint32_t)j * 16;
    cpa16(dst,        src);
    cpa16(dst + 2048, src + NOc);
    cpa16(dst + 4096, src + 2 * NOc);
    cpa16(dst + 6144, src + 3 * NOc);
    cpa_commit();
}
// Read back this thread's 8 slots from the staged buffer (LDS.128 x4, 29cy)
static __device__ __forceinline__ void readW(const ulonglong2* sW, int buf, int j,
                                             uint64_t* wpk) {
    const ulonglong2* p = sW + buf * 512 + j;
    const ulonglong2 a = p[0], b = p[128], c = p[256], d = p[384];
    wpk[0] = a.x; wpk[1] = a.y; wpk[2] = b.x; wpk[3] = b.y;
    wpk[4] = c.x; wpk[5] = c.y; wpk[6] = d.x; wpk[7] = d.y;
}

// ============================================================================
// K1: logit kernel. Block=128 (j=tid), two b's, one i-tile.
// cp.async double-buffered W pipeline; x = L' - 0.5*sum(A*v^2 + B*v).
// Barrier-free loop.
// ============================================================================
__global__ __launch_bounds__(128) void logit_kernel(const float* __restrict__ pose)
{
    __shared__ uint64_t sPoseD[2][TIc][16];                  // 8 KB
    __shared__ __align__(16) ulonglong2 sW[2 * 4 * NOc];     // 16 KB, 2 bufs

    const int j    = threadIdx.x;
    const int tile = blockIdx.x;
    const int b0   = blockIdx.y << 1;
    const int i0   = tile * TIc;
    const uint32_t sWaddr = (uint32_t)__cvta_generic_to_shared(sW);

    prefetchW(sWaddr, 0, i0, j);     // tile 0 in flight ASAP

    for (int idx = threadIdx.x; idx < 2 * TIc * 16; idx += 128) {
        const int bb = idx >> 9, rem = idx & 511;            // TIc*16 = 512
        const float f = pose[((size_t)(b0 + bb) * NIc + i0 + (rem >> 4)) * 16 + (rem & 15)];
        sPoseD[bb][rem >> 4][rem & 15] = pk2(f, f);
    }

    // per-thread A/B for 8 slots x 2 b's (loop-invariant)
    uint64_t Apk[2][8], Bpk[2][8];
    float sL[2];
    #pragma unroll
    for (int bb = 0; bb < 2; bb++) {
        const float* st = g_statsT + (size_t)(b0 + bb) * 33 * NOc;
        float Av[16], Bv[16];
        #pragma unroll
        for (int d = 0; d < 16; d++) {
            Av[d] = st[d * NOc + j];
            Bv[d] = st[(16 + d) * NOc + j];
        }
        sL[bb] = st[32 * NOc + j];
        #pragma unroll
        for (int k = 0; k < 8; k++) {
            const int pp = k >> 2, q = k & 3;
            Apk[bb][k] = pk2(Av[8 * pp + q], Av[8 * pp + q + 4]);
            Bpk[bb][k] = pk2(Bv[8 * pp + q], Bv[8 * pp + q + 4]);
        }
    }
    __syncthreads();   // pose staging visible

    #pragma unroll 1
    for (int ii = 0; ii < TIc; ii++) {
        const int buf = ii & 1;
        if (ii + 1 < TIc) {
            prefetchW(sWaddr, buf ^ 1, i0 + ii + 1, j);
            cpa_wait<1>();   // current tile resolved, next still in flight
        } else {
            cpa_wait<0>();
        }

        uint64_t wpk[8];
        readW(sW, buf, j, wpk);

        #pragma unroll
        for (int bb = 0; bb < 2; bb++) {
            uint64_t vp[8];
            votes8(wpk, sPoseD[bb][ii], vp);
            uint64_t q2a = 0ull, q2b = 0ull;
            #pragma unroll
            for (int k = 0; k < 8; k += 2) {
                const uint64_t t0 = fma2(Apk[bb][k],     vp[k],     Bpk[bb][k]);
                const uint64_t t1 = fma2(Apk[bb][k + 1], vp[k + 1], Bpk[bb][k + 1]);
                q2a = fma2(t0, vp[k],     q2a);
                q2b = fma2(t1, vp[k + 1], q2b);
            }
            float ql, qh; upk2(add2(q2a, q2b), ql, qh);
            g_x[((size_t)(b0 + bb) * NIc + i0 + ii) * NOc + j] =
                fmaf(-0.5f, ql + qh, sL[bb]);
        }
    }
}

// ============================================================================
// K2: row softmax stats. Warp per (b,i) row: writes (M, act/T).
// ============================================================================
__global__ __launch_bounds__(256) void rowmt_kernel(const float* __restrict__ act)
{
    const int row  = (blockIdx.x << 3) + (threadIdx.x >> 5);
    const int lane = threadIdx.x & 31;
    const float* xr = g_x + (size_t)row * NOc;

    const float x0 = xr[lane], x1 = xr[lane + 32], x2 = xr[lane + 64], x3 = xr[lane + 96];
    float m = fmaxf(fmaxf(x0, x1), fmaxf(x2, x3));
    #pragma unroll
    for (int off = 16; off; off >>= 1)
        m = fmaxf(m, __shfl_xor_sync(0xffffffffu, m, off));
    float s = __expf(x0 - m) + __expf(x1 - m) + __expf(x2 - m) + __expf(x3 - m);
    #pragma unroll
    for (int off = 16; off; off >>= 1)
        s += __shfl_xor_sync(0xffffffffu, s, off);
    if (lane == 0)
        g_rowMT[row] = make_float2(m, __fdividef(act[row], s));
}

// ============================================================================
// K3 / uniform pass: accumulate S0/S1/S2 partials. Same W pipeline as K1.
// Barrier-free loop.
// ============================================================================
template <bool UNIFORM>
__global__ __launch_bounds__(128) void accum_kernel(
    const float* __restrict__ pose, const float* __restrict__ act)
{
    __shared__ uint64_t sPoseD[2][TIc][16];
    __shared__ __align__(16) ulonglong2 sW[2 * 4 * NOc];
    __shared__ float    sAct[2][TIc];
    __shared__ float2   sMT[2][TIc];

    const int j    = threadIdx.x;
    const int tile = blockIdx.x;
    const int b0   = blockIdx.y << 1;
    const int i0   = tile * TIc;
    const uint32_t sWaddr = (uint32_t)__cvta_generic_to_shared(sW);

    prefetchW(sWaddr, 0, i0, j);

    for (int idx = threadIdx.x; idx < 2 * TIc * 16; idx += 128) {
        const int bb = idx >> 9, rem = idx & 511;
        const float f = pose[((size_t)(b0 + bb) * NIc + i0 + (rem >> 4)) * 16 + (rem & 15)];
        sPoseD[bb][rem >> 4][rem & 15] = pk2(f, f);
    }
    if (threadIdx.x < 2 * TIc) {
        const int bb = threadIdx.x >> 5, ii = threadIdx.x & 31;   // TIc = 32
        if (UNIFORM) sAct[bb][ii] = act[(b0 + bb) * NIc + i0 + ii];
        else         sMT[bb][ii]  = g_rowMT[(size_t)(b0 + bb) * NIc + i0 + ii];
    }
    __syncthreads();

    uint64_t S1[2][8], S2[2][8];
    float S0[2] = {0.f, 0.f};
    #pragma unroll
    for (int bb = 0; bb < 2; bb++)
        #pragma unroll
        for (int k = 0; k < 8; k++) { S1[bb][k] = 0ull; S2[bb][k] = 0ull; }

    #pragma unroll 1
    for (int ii = 0; ii < TIc; ii++) {
        const int buf = ii & 1;

        // hoist latency-bound x loads before vote math
        float xv[2];
        if (!UNIFORM) {
            #pragma unroll
            for (int bb = 0; bb < 2; bb++)
                xv[bb] = g_x[((size_t)(b0 + bb) * NIc + i0 + ii) * NOc + j];
        }

        if (ii + 1 < TIc) {
            prefetchW(sWaddr, buf ^ 1, i0 + ii + 1, j);
            cpa_wait<1>();
        } else {
            cpa_wait<0>();
        }

        uint64_t wpk[8];
        readW(sW, buf, j, wpk);

        #pragma unroll
        for (int bb = 0; bb < 2; bb++) {
            uint64_t vp[8];
            votes8(wpk, sPoseD[bb][ii], vp);
            float rp;
            if (UNIFORM) {
                rp = sAct[bb][ii] * (1.f / NOc);
            } else {
                const float2 mt = sMT[bb][ii];
                rp = __expf(xv[bb] - mt.x) * mt.y;
            }
            S0[bb] += rp;
            const uint64_t rpp = pk2(rp, rp);
            #pragma unroll
            for (int k = 0; k < 8; k++) {
                const uint64_t tmp = mul2(rpp, vp[k]);
                S1[bb][k] = add2(S1[bb][k], tmp);
                S2[bb][k] = fma2(tmp, vp[k], S2[bb][k]);
            }
        }
    }

    #pragma unroll
    for (int bb = 0; bb < 2; bb++) {
        float* pb = g_part + ((size_t)((b0 + bb) * NTc + tile) * NOc + j) * RW;
        pb[0] = S0[bb];
        #pragma unroll
        for (int k = 0; k < 8; k++) {
            *(uint64_t*)(pb + 4  + 2 * k) = S1[bb][k];
            *(uint64_t*)(pb + 20 + 2 * k) = S2[bb][k];
        }
    }
}

// ============================================================================
// Stats kernel: one warp per (b, j); lane = stat slot; coalesced tile loop.
// Emits A/B/L' for the next pass (or the final outputs).
// ============================================================================
template <bool FINAL>
__global__ __launch_bounds__(256) void stats_kernel(
    const float* __restrict__ beta_v,
    const float* __restrict__ beta_a,
    float lam,
    float* __restrict__ out)
{
    const int warp = (blockIdx.x * blockDim.x + threadIdx.x) >> 5;
    const int lane = threadIdx.x & 31;
    const int b = warp >> 7;
    const int j = warp & 127;

    const float* base = g_part + ((size_t)b * NTc * NOc + j) * RW;
    float acc = 0.f, acc2 = 0.f;
    #pragma unroll 4
    for (int tile = 0; tile < NTc; tile++) {
        const float* row = base + (size_t)tile * (NOc * RW);
        acc += row[lane];
        if (lane < 4) acc2 += row[32 + lane];
    }

    const int d  = lane & 15;
    const int q  = d & 3, pp = (d >> 3) & 1, hd = (d >> 2) & 1;
    const int sl = 8 * pp + 2 * q + hd;
    const float S0  = __shfl_sync(0xffffffffu, acc, 0);
    const float S1d = __shfl_sync(0xffffffffu, acc, 4 + sl);
    const float s2a = __shfl_sync(0xffffffffu, acc, (20 + sl) & 31);
    const float s2b = __shfl_sync(0xffffffffu, acc2, (sl >= 12) ? (sl - 12) : 0);
    const float S2d = (sl < 12) ? s2a : s2b;

    const float Rs = S0 + EPSf;
    const float invRs = 1.f / Rs;
    const float muv = S1d * invRs;
    const float srp = S2d - 2.f * muv * S1d + muv * muv * S0;  // exact expansion
    const float sig = srp * invRs + EPSf;
    const float A   = 1.f / sig;
    const float lg  = logf(sig);
    float logsum = lg;
    #pragma unroll
    for (int off = 8; off; off >>= 1)
        logsum += __shfl_xor_sync(0xffffffffu, logsum, off);
    float muq = muv * muv * A;          // for L' correction
    #pragma unroll
    for (int off = 8; off; off >>= 1)
        muq += __shfl_xor_sync(0xffffffffu, muq, off);

    const float cost = (16.f * beta_v[j] + 0.5f * logsum) * Rs;
    const float aout = 1.f / (1.f + expf(-(lam * (beta_a[j] - cost))));

    if (FINAL) {
        if (lane < 16) out[(size_t)(b * NOc + j) * 16 + d] = muv;
        if (lane == 0) out[(size_t)Bn * NOc * 16 + b * NOc + j] = aout;
    } else {
        float* st = g_statsT + (size_t)b * 33 * NOc;
        if (lane < 16) {
            st[d * NOc + j]        = A;                 // A = 1/sig
            st[(16 + d) * NOc + j] = -2.f * muv * A;    // B = -2mu/sig
        }
        if (lane == 0)
            st[32 * NOc + j] = logf(aout + EPSf) - 0.5f * logsum
                               - 8.f * LOG2PIf - 0.5f * muq;   // L'
    }
}

extern "C" void kernel_launch(void* const* d_in, const int* in_sizes, int n_in,
                              void* d_out, int out_size) {
    const float* pose   = (const float*)d_in[0];
    const float* act    = (const float*)d_in[1];
    const float* W      = (const float*)d_in[2];
    const float* beta_v = (const float*)d_in[3];
    const float* beta_a = (const float*)d_in[4];
    float* out = (float*)d_out;

    dim3 gp(NTc, Bn / 2);                       // 64 x 16 blocks of 128
    const int rgrid = (Bn * NIc) / 8;           // 8192 blocks of 256 (warp/row)
    const int sgrid = (Bn * NOc * 32) / 256;    // 512 blocks of 256

    wt_kernel<<<NIc, 128>>>(W);                 // pack+transpose W once

    // t=0: uniform R
    accum_kernel<true><<<gp, 128>>>(pose, act);
    stats_kernel<false><<<sgrid, 256>>>(beta_v, beta_a, LAM1, out);
    // t=1
    logit_kernel<<<gp, 128>>>(pose);
    rowmt_kernel<<<rgrid, 256>>>(act);
    accum_kernel<false><<<gp, 128>>>(pose, act);
    stats_kernel<false><<<sgrid, 256>>>(beta_v, beta_a, LAM2, out);
    // t=2
    logit_kernel<<<gp, 128>>>(pose);
    rowmt_kernel<<<rgrid, 256>>>(act);
    accum_kernel<false><<<gp, 128>>>(pose, act);
    stats_kernel<true><<<sgrid, 256>>>(beta_v, beta_a, LAM3, out);
}

// round 12
// speedup vs baseline: 1.2614x; 1.0650x over previous
#include <cuda_runtime.h>
#include <math.h>
#include <stdint.h>

// Problem constants
#define Bn   32
#define NIc  2048
#define NOc  128
#define TIc  32              // i's per block in pass kernels
#define NTc  (NIc / TIc)     // 64 tiles
#define RW   36              // g_part row: [0]=S0, [4..19]=S1(permuted), [20..35]=S2(permuted)
#define EPSf 1e-9f
#define LOG2PIf 1.8378770664093453f

#define LAM1 0.0005f
#define LAM2 0.000975f
#define LAM3 0.00142625f

// Module-static scratch (allocation-free, deterministic)
__device__ __align__(16) float g_part[(size_t)Bn * NTc * NOc * RW];     // 37.7 MB
// g_statsT[b][s][j]: s 0..15 = A(d)=1/sig, 16..31 = B(d)=-2mu/sig, 32 = L'
__device__ __align__(16) float g_statsT[(size_t)Bn * 33 * NOc];
// Transposed+packed W: [i][k2][j] -> ulonglong2 = slots (2*k2, 2*k2+1)
// slot k=pp*4+r holds (W[i][j][2pp][r], W[i][j][2pp+1][r])
__device__ __align__(16) ulonglong2 g_Wt[(size_t)NIc * 4 * NOc];        // 16.8 MB

// ---------------- f32x2 packed helpers ----------------
static __device__ __forceinline__ uint64_t pk2(float lo, float hi) {
    uint64_t r; asm("mov.b64 %0, {%1, %2};" : "=l"(r) : "f"(lo), "f"(hi)); return r;
}
static __device__ __forceinline__ void upk2(uint64_t v, float& lo, float& hi) {
    asm("mov.b64 {%0, %1}, %2;" : "=f"(lo), "=f"(hi) : "l"(v));
}
static __device__ __forceinline__ uint64_t fma2(uint64_t a, uint64_t b, uint64_t c) {
    uint64_t d; asm("fma.rn.f32x2 %0, %1, %2, %3;" : "=l"(d) : "l"(a), "l"(b), "l"(c)); return d;
}
static __device__ __forceinline__ uint64_t mul2(uint64_t a, uint64_t b) {
    uint64_t d; asm("mul.rn.f32x2 %0, %1, %2;" : "=l"(d) : "l"(a), "l"(b)); return d;
}
static __device__ __forceinline__ uint64_t add2(uint64_t a, uint64_t b) {
    uint64_t d; asm("add.rn.f32x2 %0, %1, %2;" : "=l"(d) : "l"(a), "l"(b)); return d;
}

// ---------------- cp.async helpers ----------------
static __device__ __forceinline__ void cpa16(uint32_t smem_dst, const void* gsrc) {
    asm volatile("cp.async.cg.shared.global [%0], [%1], 16;" :: "r"(smem_dst), "l"(gsrc));
}
static __device__ __forceinline__ void cpa_commit() {
    asm volatile("cp.async.commit_group;");
}
template <int N> static __device__ __forceinline__ void cpa_wait() {
    asm volatile("cp.async.wait_group %0;" :: "n"(N));
}

// votes: slot k=(pp*4+q) = (v[8pp+q], v[8pp+q+4]); wpk[pp*4+r]=(W[2pp][r],W[2pp+1][r]);
// pd[4r+q] = dup-packed pose (pose[r][q], pose[r][q])
static __device__ __forceinline__ void votes8(const uint64_t* __restrict__ wpk,
                                              const uint64_t* __restrict__ pd,
                                              uint64_t* __restrict__ vp) {
    #pragma unroll
    for (int k = 0; k < 8; k++) {
        const int pp = k >> 2, q = k & 3;
        uint64_t a = mul2(wpk[pp * 4 + 0], pd[0 + q]);
        a = fma2(wpk[pp * 4 + 1], pd[4 + q], a);
        a = fma2(wpk[pp * 4 + 2], pd[8 + q], a);
        vp[k] = fma2(wpk[pp * 4 + 3], pd[12 + q], a);
    }
}

// ============================================================================
// W transpose+pack kernel (once per launch). Block=128 (j=tid), grid=NIc.
// ============================================================================
__global__ __launch_bounds__(128) void wt_kernel(const float* __restrict__ W) {
    const int i = blockIdx.x;
    const int j = threadIdx.x;
    const float4* wr = (const float4*)(W + ((size_t)i * NOc + j) * 16);
    const float4 w0 = wr[0], w1 = wr[1], w2 = wr[2], w3 = wr[3];
    ulonglong2* out = g_Wt + (size_t)i * 4 * NOc + j;
    out[0]        = make_ulonglong2(pk2(w0.x, w1.x), pk2(w0.y, w1.y));
    out[NOc]      = make_ulonglong2(pk2(w0.z, w1.z), pk2(w0.w, w1.w));
    out[2 * NOc]  = make_ulonglong2(pk2(w2.x, w3.x), pk2(w2.y, w3.y));
    out[3 * NOc]  = make_ulonglong2(pk2(w2.z, w3.z), pk2(w2.w, w3.w));
}

// Per-thread W prefetch: thread j stages ITS OWN 4x16B chunks of tile i.
// No cross-thread deps -> no barrier needed, wait_group only.
static __device__ __forceinline__ void prefetchW(uint32_t sWaddr, int buf, int i, int j) {
    const ulonglong2* src = g_Wt + (size_t)i * 4 * NOc + j;
    const uint32_t dst = sWaddr + (uint32_t)buf * 8192 + (uint32_t)j * 16;
    cpa16(dst,        src);
    cpa16(dst + 2048, src + NOc);
    cpa16(dst + 4096, src + 2 * NOc);
    cpa16(dst + 6144, src + 3 * NOc);
    cpa_commit();
}
static __device__ __forceinline__ void readW(const ulonglong2* sW, int buf, int j,
                                             uint64_t* wpk) {
    const ulonglong2* p = sW + buf * 512 + j;
    const ulonglong2 a = p[0], b = p[128], c = p[256], d = p[384];
    wpk[0] = a.x; wpk[1] = a.y; wpk[2] = b.x; wpk[3] = b.y;
    wpk[4] = c.x; wpk[5] = c.y; wpk[6] = d.x; wpk[7] = d.y;
}

// ============================================================================
// Fused pass kernel. Block = 128 threads (j = tid), two b's, one i-tile.
// Non-uniform: sweep1 computes logits into smem sX, in-block parallel row
// softmax (4 warps x 16 rows), sweep2 accumulates S0/S1/S2 with
// rp = exp(x - M) * (act/T). Uniform: accumulate-only with rp = act/NO.
// cp.async double-buffered W pipeline in each sweep; 2 barriers total.
// ============================================================================
template <bool UNIFORM>
__global__ __launch_bounds__(128) void fused_kernel(
    const float* __restrict__ pose, const float* __restrict__ act)
{
    __shared__ uint64_t sPoseD[2][TIc][16];                  // 8 KB
    __shared__ __align__(16) ulonglong2 sW[2 * 4 * NOc];     // 16 KB
    __shared__ float2   sMT[2][TIc];                         // (M, a/T) or (a/NO, -)
    extern __shared__ float sX[];                            // [2][TIc][NOc] non-uniform

    const int j    = threadIdx.x;
    const int tile = blockIdx.x;
    const int b0   = blockIdx.y << 1;
    const int i0   = tile * TIc;
    const uint32_t sWaddr = (uint32_t)__cvta_generic_to_shared(sW);

    prefetchW(sWaddr, 0, i0, j);     // tile 0 in flight ASAP

    for (int idx = j; idx < 2 * TIc * 16; idx += 128) {
        const int bb = idx >> 9, rem = idx & 511;            // TIc*16 = 512
        const float f = pose[((size_t)(b0 + bb) * NIc + i0 + (rem >> 4)) * 16 + (rem & 15)];
        sPoseD[bb][rem >> 4][rem & 15] = pk2(f, f);
    }
    if (UNIFORM && j < 2 * TIc) {
        const int bb = j >> 5, ii = j & 31;                  // TIc = 32
        sMT[bb][ii].x = act[(b0 + bb) * NIc + i0 + ii] * (1.f / NOc);
    }
    __syncthreads();   // pose (and uniform sMT) visible

    if (!UNIFORM) {
        // ---- Sweep 1: logits into sX ----
        {
            uint64_t Apk[2][8], Bpk[2][8];
            float sL[2];
            #pragma unroll
            for (int bb = 0; bb < 2; bb++) {
                const float* st = g_statsT + (size_t)(b0 + bb) * 33 * NOc;
                float Av[16], Bv[16];
                #pragma unroll
                for (int d = 0; d < 16; d++) {
                    Av[d] = st[d * NOc + j];
                    Bv[d] = st[(16 + d) * NOc + j];
                }
                sL[bb] = st[32 * NOc + j];
                #pragma unroll
                for (int k = 0; k < 8; k++) {
                    const int pp = k >> 2, q = k & 3;
                    Apk[bb][k] = pk2(Av[8 * pp + q], Av[8 * pp + q + 4]);
                    Bpk[bb][k] = pk2(Bv[8 * pp + q], Bv[8 * pp + q + 4]);
                }
            }

            #pragma unroll 1
            for (int ii = 0; ii < TIc; ii++) {
                const int buf = ii & 1;
                if (ii + 1 < TIc) { prefetchW(sWaddr, buf ^ 1, i0 + ii + 1, j); cpa_wait<1>(); }
                else              { cpa_wait<0>(); }

                uint64_t wpk[8];
                readW(sW, buf, j, wpk);

                #pragma unroll
                for (int bb = 0; bb < 2; bb++) {
                    uint64_t vp[8];
                    votes8(wpk, sPoseD[bb][ii], vp);
                    uint64_t q2a = 0ull, q2b = 0ull;
                    #pragma unroll
                    for (int k = 0; k < 8; k += 2) {
                        const uint64_t t0 = fma2(Apk[bb][k],     vp[k],     Bpk[bb][k]);
                        const uint64_t t1 = fma2(Apk[bb][k + 1], vp[k + 1], Bpk[bb][k + 1]);
                        q2a = fma2(t0, vp[k],     q2a);
                        q2b = fma2(t1, vp[k + 1], q2b);
                    }
                    float ql, qh; upk2(add2(q2a, q2b), ql, qh);
                    sX[(bb * TIc + ii) * NOc + j] = fmaf(-0.5f, ql + qh, sL[bb]);
                }
            }
        }
        __syncthreads();   // sX complete

        // ---- Softmax phase: warp w handles rows w*16 .. w*16+15 ----
        {
            const int w = j >> 5, lane = j & 31;
            float actv = 0.f;
            if (lane < 16) {
                const int r = w * 16 + lane, bb = r >> 5, ii = r & 31;
                actv = act[(b0 + bb) * NIc + i0 + ii];
            }
            #pragma unroll 4
            for (int k = 0; k < 16; k++) {
                const int r = w * 16 + k, bb = r >> 5, ii = r & 31;
                const float* xr = sX + (bb * TIc + ii) * NOc;
                const float x0 = xr[lane], x1 = xr[lane + 32],
                            x2 = xr[lane + 64], x3 = xr[lane + 96];
                float m = fmaxf(fmaxf(x0, x1), fmaxf(x2, x3));
                #pragma unroll
                for (int off = 16; off; off >>= 1)
                    m = fmaxf(m, __shfl_xor_sync(0xffffffffu, m, off));
                float s = __expf(x0 - m) + __expf(x1 - m) + __expf(x2 - m) + __expf(x3 - m);
                #pragma unroll
                for (int off = 16; off; off >>= 1)
                    s += __shfl_xor_sync(0xffffffffu, s, off);
                const float a = __shfl_sync(0xffffffffu, actv, k);
                if (lane == 0)
                    sMT[bb][ii] = make_float2(m, __fdividef(a, s));
            }
        }
        __syncthreads();   // sMT complete

        prefetchW(sWaddr, 0, i0, j);   // re-prime pipeline for sweep 2
    }

    // ---- Sweep 2: accumulate S0/S1/S2 ----
    uint64_t S1[2][8], S2[2][8];
    float S0[2] = {0.f, 0.f};
    #pragma unroll
    for (int bb = 0; bb < 2; bb++)
        #pragma unroll
        for (int k = 0; k < 8; k++) { S1[bb][k] = 0ull; S2[bb][k] = 0ull; }

    #pragma unroll 1
    for (int ii = 0; ii < TIc; ii++) {
        const int buf = ii & 1;
        if (ii + 1 < TIc) { prefetchW(sWaddr, buf ^ 1, i0 + ii + 1, j); cpa_wait<1>(); }
        else              { cpa_wait<0>(); }

        uint64_t wpk[8];
        readW(sW, buf, j, wpk);

        #pragma unroll
        for (int bb = 0; bb < 2; bb++) {
            float rp;
            if (UNIFORM) {
                rp = sMT[bb][ii].x;
            } else {
                const float x = sX[(bb * TIc + ii) * NOc + j];
                const float2 mt = sMT[bb][ii];
                rp = __expf(x - mt.x) * mt.y;
            }
            uint64_t vp[8];
            votes8(wpk, sPoseD[bb][ii], vp);
            S0[bb] += rp;
            const uint64_t rpp = pk2(rp, rp);
            #pragma unroll
            for (int k = 0; k < 8; k++) {
                const uint64_t tmp = mul2(rpp, vp[k]);
                S1[bb][k] = add2(S1[bb][k], tmp);
                S2[bb][k] = fma2(tmp, vp[k], S2[bb][k]);
            }
        }
    }

    #pragma unroll
    for (int bb = 0; bb < 2; bb++) {
        float* pb = g_part + ((size_t)((b0 + bb) * NTc + tile) * NOc + j) * RW;
        pb[0] = S0[bb];
        #pragma unroll
        for (int k = 0; k < 8; k++) {
            *(uint64_t*)(pb + 4  + 2 * k) = S1[bb][k];
            *(uint64_t*)(pb + 20 + 2 * k) = S2[bb][k];
        }
    }
}

// ============================================================================
// Stats kernel: one warp per (b, j); lane = stat slot; coalesced tile loop.
// Emits A/B/L' for the next pass (or the final outputs).
// ============================================================================
template <bool FINAL>
__global__ __launch_bounds__(256) void stats_kernel(
    const float* __restrict__ beta_v,
    const float* __restrict__ beta_a,
    float lam,
    float* __restrict__ out)
{
    const int warp = (blockIdx.x * blockDim.x + threadIdx.x) >> 5;
    const int lane = threadIdx.x & 31;
    const int b = warp >> 7;
    const int j = warp & 127;

    const float* base = g_part + ((size_t)b * NTc * NOc + j) * RW;
    float acc = 0.f, acc2 = 0.f;
    #pragma unroll 4
    for (int tile = 0; tile < NTc; tile++) {
        const float* row = base + (size_t)tile * (NOc * RW);
        acc += row[lane];
        if (lane < 4) acc2 += row[32 + lane];
    }

    const int d  = lane & 15;
    const int q  = d & 3, pp = (d >> 3) & 1, hd = (d >> 2) & 1;
    const int sl = 8 * pp + 2 * q + hd;
    const float S0  = __shfl_sync(0xffffffffu, acc, 0);
    const float S1d = __shfl_sync(0xffffffffu, acc, 4 + sl);
    const float s2a = __shfl_sync(0xffffffffu, acc, (20 + sl) & 31);
    const float s2b = __shfl_sync(0xffffffffu, acc2, (sl >= 12) ? (sl - 12) : 0);
    const float S2d = (sl < 12) ? s2a : s2b;

    const float Rs = S0 + EPSf;
    const float invRs = 1.f / Rs;
    const float muv = S1d * invRs;
    const float srp = S2d - 2.f * muv * S1d + muv * muv * S0;  // exact expansion
    const float sig = srp * invRs + EPSf;
    const float A   = 1.f / sig;
    const float lg  = logf(sig);
    float logsum = lg;
    #pragma unroll
    for (int off = 8; off; off >>= 1)
        logsum += __shfl_xor_sync(0xffffffffu, logsum, off);
    float muq = muv * muv * A;          // for L' correction
    #pragma unroll
    for (int off = 8; off; off >>= 1)
        muq += __shfl_xor_sync(0xffffffffu, muq, off);

    const float cost = (16.f * beta_v[j] + 0.5f * logsum) * Rs;
    const float aout = 1.f / (1.f + expf(-(lam * (beta_a[j] - cost))));

    if (FINAL) {
        if (lane < 16) out[(size_t)(b * NOc + j) * 16 + d] = muv;
        if (lane == 0) out[(size_t)Bn * NOc * 16 + b * NOc + j] = aout;
    } else {
        float* st = g_statsT + (size_t)b * 33 * NOc;
        if (lane < 16) {
            st[d * NOc + j]        = A;                 // A = 1/sig
            st[(16 + d) * NOc + j] = -2.f * muv * A;    // B = -2mu/sig
        }
        if (lane == 0)
            st[32 * NOc + j] = logf(aout + EPSf) - 0.5f * logsum
                               - 8.f * LOG2PIf - 0.5f * muq;   // L'
    }
}

extern "C" void kernel_launch(void* const* d_in, const int* in_sizes, int n_in,
                              void* d_out, int out_size) {
    const float* pose   = (const float*)d_in[0];
    const float* act    = (const float*)d_in[1];
    const float* W      = (const float*)d_in[2];
    const float* beta_v = (const float*)d_in[3];
    const float* beta_a = (const float*)d_in[4];
    float* out = (float*)d_out;

    dim3 gp(NTc, Bn / 2);                        // 64 x 16 blocks of 128
    const int sgrid = (Bn * NOc * 32) / 256;     // 512 blocks of 256
    const size_t dynX = 2 * TIc * NOc * sizeof(float);   // 32 KB dynamic sX

    // Raise the dynamic-smem cap for the non-uniform fused kernel
    // (static 24.6 KB + dynamic 32 KB > 48 KB default). Attribute setter:
    // not a stream op / alloc / sync -> graph-capture safe, idempotent.
    cudaFuncSetAttribute((const void*)fused_kernel<false>,
                         cudaFuncAttributeMaxDynamicSharedMemorySize, (int)dynX);

    wt_kernel<<<NIc, 128>>>(W);                  // pack+transpose W once

    // t=0: uniform R (accumulate only)
    fused_kernel<true><<<gp, 128>>>(pose, act);
    stats_kernel<false><<<sgrid, 256>>>(beta_v, beta_a, LAM1, out);
    // t=1: logits + in-block softmax + accumulate
    fused_kernel<false><<<gp, 128, dynX>>>(pose, act);
    stats_kernel<false><<<sgrid, 256>>>(beta_v, beta_a, LAM2, out);
    // t=2
    fused_kernel<false><<<gp, 128, dynX>>>(pose, act);
    stats_kernel<true><<<sgrid, 256>>>(beta_v, beta_a, LAM3, out);
}

// round 13
// speedup vs baseline: 1.3487x; 1.0692x over previous
#include <cuda_runtime.h>
#include <math.h>
#include <stdint.h>

// Problem constants
#define Bn   32
#define NIc  2048
#define NOc  128
#define TIc  32              // i's per block in pass kernels
#define NTc  (NIc / TIc)     // 64 tiles
#define RW   36              // g_part row: [0]=S0, [4..19]=S1(permuted), [20..35]=S2(permuted)
#define EPSf 1e-9f
#define LOG2PIf 1.8378770664093453f

#define LAM1 0.0005f
#define LAM2 0.000975f
#define LAM3 0.00142625f

// Module-static scratch (allocation-free, deterministic)
__device__ __align__(16) float g_part[(size_t)Bn * NTc * NOc * RW];     // 37.7 MB
// g_statsT[b][s][j]: s 0..15 = A(d)=1/sig, 16..31 = B(d)=-2mu/sig, 32 = L'
__device__ __align__(16) float g_statsT[(size_t)Bn * 33 * NOc];
// Transposed+packed W: [i][k2][j] -> ulonglong2 = slots (2*k2, 2*k2+1)
// slot k=pp*4+r holds (W[i][j][2pp][r], W[i][j][2pp+1][r])
__device__ __align__(16) ulonglong2 g_Wt[(size_t)NIc * 4 * NOc];        // 16.8 MB

// ---------------- f32x2 packed helpers ----------------
static __device__ __forceinline__ uint64_t pk2(float lo, float hi) {
    uint64_t r; asm("mov.b64 %0, {%1, %2};" : "=l"(r) : "f"(lo), "f"(hi)); return r;
}
static __device__ __forceinline__ void upk2(uint64_t v, float& lo, float& hi) {
    asm("mov.b64 {%0, %1}, %2;" : "=f"(lo), "=f"(hi) : "l"(v));
}
static __device__ __forceinline__ uint64_t fma2(uint64_t a, uint64_t b, uint64_t c) {
    uint64_t d; asm("fma.rn.f32x2 %0, %1, %2, %3;" : "=l"(d) : "l"(a), "l"(b), "l"(c)); return d;
}
static __device__ __forceinline__ uint64_t mul2(uint64_t a, uint64_t b) {
    uint64_t d; asm("mul.rn.f32x2 %0, %1, %2;" : "=l"(d) : "l"(a), "l"(b)); return d;
}
static __device__ __forceinline__ uint64_t add2(uint64_t a, uint64_t b) {
    uint64_t d; asm("add.rn.f32x2 %0, %1, %2;" : "=l"(d) : "l"(a), "l"(b)); return d;
}

// ---------------- cp.async helpers ----------------
static __device__ __forceinline__ void cpa16(uint32_t smem_dst, const void* gsrc) {
    asm volatile("cp.async.cg.shared.global [%0], [%1], 16;" :: "r"(smem_dst), "l"(gsrc));
}
static __device__ __forceinline__ void cpa_commit() {
    asm volatile("cp.async.commit_group;");
}
template <int N> static __device__ __forceinline__ void cpa_wait() {
    asm volatile("cp.async.wait_group %0;" :: "n"(N));
}

// votes: slot k=(pp*4+q) = (v[8pp+q], v[8pp+q+4]); wpk[pp*4+r]=(W[2pp][r],W[2pp+1][r]);
// pd[4r+q] = dup-packed pose (pose[r][q], pose[r][q])
static __device__ __forceinline__ void votes8(const uint64_t* __restrict__ wpk,
                                              const uint64_t* __restrict__ pd,
                                              uint64_t* __restrict__ vp) {
    #pragma unroll
    for (int k = 0; k < 8; k++) {
        const int pp = k >> 2, q = k & 3;
        uint64_t a = mul2(wpk[pp * 4 + 0], pd[0 + q]);
        a = fma2(wpk[pp * 4 + 1], pd[4 + q], a);
        a = fma2(wpk[pp * 4 + 2], pd[8 + q], a);
        vp[k] = fma2(wpk[pp * 4 + 3], pd[12 + q], a);
    }
}

// ============================================================================
// W transpose+pack kernel (once per launch). Block=128 (j=tid), grid=NIc.
// ============================================================================
__global__ __launch_bounds__(128) void wt_kernel(const float* __restrict__ W) {
    const int i = blockIdx.x;
    const int j = threadIdx.x;
    const float4* wr = (const float4*)(W + ((size_t)i * NOc + j) * 16);
    const float4 w0 = wr[0], w1 = wr[1], w2 = wr[2], w3 = wr[3];
    ulonglong2* out = g_Wt + (size_t)i * 4 * NOc + j;
    out[0]        = make_ulonglong2(pk2(w0.x, w1.x), pk2(w0.y, w1.y));
    out[NOc]      = make_ulonglong2(pk2(w0.z, w1.z), pk2(w0.w, w1.w));
    out[2 * NOc]  = make_ulonglong2(pk2(w2.x, w3.x), pk2(w2.y, w3.y));
    out[3 * NOc]  = make_ulonglong2(pk2(w2.z, w3.z), pk2(w2.w, w3.w));
}

// Per-thread W prefetch: thread j stages ITS OWN 4x16B chunks of tile i.
// sW columns are strictly per-thread-private -> no cross-thread hazards,
// no barrier needed; cp.async.wait_group is the only sync.
static __device__ __forceinline__ void prefetchW(uint32_t sWaddr, int buf, int i, int j) {
    const ulonglong2* src = g_Wt + (size_t)i * 4 * NOc + j;
    const uint32_t dst = sWaddr + (uint32_t)buf * 8192 + (uint32_t)j * 16;
    cpa16(dst,        src);
    cpa16(dst + 2048, src + NOc);
    cpa16(dst + 4096, src + 2 * NOc);
    cpa16(dst + 6144, src + 3 * NOc);
    cpa_commit();
}
static __device__ __forceinline__ void readW(const ulonglong2* sW, int buf, int j,
                                             uint64_t* wpk) {
    const ulonglong2* p = sW + buf * 512 + j;
    const ulonglong2 a = p[0], b = p[128], c = p[256], d = p[384];
    wpk[0] = a.x; wpk[1] = a.y; wpk[2] = b.x; wpk[3] = b.y;
    wpk[4] = c.x; wpk[5] = c.y; wpk[6] = d.x; wpk[7] = d.y;
}

// ============================================================================
// Fused pass kernel. Block = 128 threads (j = tid), two b's, one i-tile.
// Non-uniform: sweep1 computes logits into dynamic smem sX, the softmax phase
// REWRITES sX in place with rp = exp(x - M) * (act/T) (reusing the exps
// already computed for the row sum), sweep2 reads rp with one LDS.32 and
// accumulates S0/S1/S2. Uniform: sX (256B dynamic) holds act/NO per row.
// Static smem = 24 KB exactly; +32 KB dynamic + 1 KB reserved = 4 blocks/SM.
// cp.async double-buffered W pipeline in each sweep; 2 barriers total.
// ============================================================================
template <bool UNIFORM>
__global__ __launch_bounds__(128) void fused_kernel(
    const float* __restrict__ pose, const float* __restrict__ act)
{
    __shared__ uint64_t sPoseD[2][TIc][16];                  // 8 KB
    __shared__ __align__(16) ulonglong2 sW[2 * 4 * NOc];     // 16 KB
    extern __shared__ float sX[];   // non-uniform: [2*TIc][NOc]; uniform: [2*TIc]

    const int j    = threadIdx.x;
    const int tile = blockIdx.x;
    const int b0   = blockIdx.y << 1;
    const int i0   = tile * TIc;
    const uint32_t sWaddr = (uint32_t)__cvta_generic_to_shared(sW);

    prefetchW(sWaddr, 0, i0, j);     // tile 0 in flight ASAP

    for (int idx = j; idx < 2 * TIc * 16; idx += 128) {
        const int bb = idx >> 9, rem = idx & 511;            // TIc*16 = 512
        const float f = pose[((size_t)(b0 + bb) * NIc + i0 + (rem >> 4)) * 16 + (rem & 15)];
        sPoseD[bb][rem >> 4][rem & 15] = pk2(f, f);
    }
    if (UNIFORM && j < 2 * TIc) {
        const int bb = j >> 5, ii = j & 31;                  // row r = j
        sX[j] = act[(b0 + bb) * NIc + i0 + ii] * (1.f / NOc);
    }
    __syncthreads();   // pose (and uniform sX) visible

    if (!UNIFORM) {
        // ---- Sweep 1: logits into sX ----
        {
            uint64_t Apk[2][8], Bpk[2][8];
            float sL[2];
            #pragma unroll
            for (int bb = 0; bb < 2; bb++) {
                const float* st = g_statsT + (size_t)(b0 + bb) * 33 * NOc;
                float Av[16], Bv[16];
                #pragma unroll
                for (int d = 0; d < 16; d++) {
                    Av[d] = st[d * NOc + j];
                    Bv[d] = st[(16 + d) * NOc + j];
                }
                sL[bb] = st[32 * NOc + j];
                #pragma unroll
                for (int k = 0; k < 8; k++) {
                    const int pp = k >> 2, q = k & 3;
                    Apk[bb][k] = pk2(Av[8 * pp + q], Av[8 * pp + q + 4]);
                    Bpk[bb][k] = pk2(Bv[8 * pp + q], Bv[8 * pp + q + 4]);
                }
            }

            #pragma unroll 1
            for (int ii = 0; ii < TIc; ii++) {
                const int buf = ii & 1;
                if (ii + 1 < TIc) { prefetchW(sWaddr, buf ^ 1, i0 + ii + 1, j); cpa_wait<1>(); }
                else              { cpa_wait<0>(); }

                uint64_t wpk[8];
                readW(sW, buf, j, wpk);

                #pragma unroll
                for (int bb = 0; bb < 2; bb++) {
                    uint64_t vp[8];
                    votes8(wpk, sPoseD[bb][ii], vp);
                    uint64_t q2a = 0ull, q2b = 0ull;
                    #pragma unroll
                    for (int k = 0; k < 8; k += 2) {
                        const uint64_t t0 = fma2(Apk[bb][k],     vp[k],     Bpk[bb][k]);
                        const uint64_t t1 = fma2(Apk[bb][k + 1], vp[k + 1], Bpk[bb][k + 1]);
                        q2a = fma2(t0, vp[k],     q2a);
                        q2b = fma2(t1, vp[k + 1], q2b);
                    }
                    float ql, qh; upk2(add2(q2a, q2b), ql, qh);
                    sX[(bb * TIc + ii) * NOc + j] = fmaf(-0.5f, ql + qh, sL[bb]);
                }
            }
        }
        // prime sweep-2 pipeline NOW: sW columns are per-thread-private, so
        // this is safe pre-barrier and the latency hides under the softmax.
        prefetchW(sWaddr, 0, i0, j);
        __syncthreads();   // sX complete

        // ---- Softmax phase: warp w handles rows w*16 .. w*16+15; rewrites
        //      sX in place with rp = exp(x - M) * (act/T). ----
        {
            const int w = j >> 5, lane = j & 31;
            float actv = 0.f;
            if (lane < 16) {
                const int r = w * 16 + lane, bb = r >> 5, ii = r & 31;
                actv = act[(b0 + bb) * NIc + i0 + ii];
            }
            #pragma unroll 4
            for (int k = 0; k < 16; k++) {
                const int r = w * 16 + k, bb = r >> 5, ii = r & 31;
                float* xr = sX + (bb * TIc + ii) * NOc;
                const float x0 = xr[lane], x1 = xr[lane + 32],
                            x2 = xr[lane + 64], x3 = xr[lane + 96];
                float m = fmaxf(fmaxf(x0, x1), fmaxf(x2, x3));
                #pragma unroll
                for (int off = 16; off; off >>= 1)
                    m = fmaxf(m, __shfl_xor_sync(0xffffffffu, m, off));
                const float e0 = __expf(x0 - m), e1 = __expf(x1 - m),
                            e2 = __expf(x2 - m), e3 = __expf(x3 - m);
                float s = e0 + e1 + e2 + e3;
                #pragma unroll
                for (int off = 16; off; off >>= 1)
                    s += __shfl_xor_sync(0xffffffffu, s, off);
                const float a = __shfl_sync(0xffffffffu, actv, k);
                const float c = __fdividef(a, s);
                xr[lane]      = e0 * c;
                xr[lane + 32] = e1 * c;
                xr[lane + 64] = e2 * c;
                xr[lane + 96] = e3 * c;
            }
        }
        __syncthreads();   // rp values complete
    }

    // ---- Sweep 2: accumulate S0/S1/S2 ----
    uint64_t S1[2][8], S2[2][8];
    float S0[2] = {0.f, 0.f};
    #pragma unroll
    for (int bb = 0; bb < 2; bb++)
        #pragma unroll
        for (int k = 0; k < 8; k++) { S1[bb][k] = 0ull; S2[bb][k] = 0ull; }

    #pragma unroll 1
    for (int ii = 0; ii < TIc; ii++) {
        const int buf = ii & 1;
        if (ii + 1 < TIc) { prefetchW(sWaddr, buf ^ 1, i0 + ii + 1, j); cpa_wait<1>(); }
        else              { cpa_wait<0>(); }

        uint64_t wpk[8];
        readW(sW, buf, j, wpk);

        #pragma unroll
        for (int bb = 0; bb < 2; bb++) {
            const float rp = UNIFORM ? sX[bb * TIc + ii]
                                     : sX[(bb * TIc + ii) * NOc + j];
            uint64_t vp[8];
            votes8(wpk, sPoseD[bb][ii], vp);
            S0[bb] += rp;
            const uint64_t rpp = pk2(rp, rp);
            #pragma unroll
            for (int k = 0; k < 8; k++) {
                const uint64_t tmp = mul2(rpp, vp[k]);
                S1[bb][k] = add2(S1[bb][k], tmp);
                S2[bb][k] = fma2(tmp, vp[k], S2[bb][k]);
            }
        }
    }

    #pragma unroll
    for (int bb = 0; bb < 2; bb++) {
        float* pb = g_part + ((size_t)((b0 + bb) * NTc + tile) * NOc + j) * RW;
        pb[0] = S0[bb];
        #pragma unroll
        for (int k = 0; k < 8; k++) {
            *(uint64_t*)(pb + 4  + 2 * k) = S1[bb][k];
            *(uint64_t*)(pb + 20 + 2 * k) = S2[bb][k];
        }
    }
}

// ============================================================================
// Stats kernel: one warp per (b, j); lane = stat slot; coalesced tile loop.
// Emits A/B/L' for the next pass (or the final outputs).
// ============================================================================
template <bool FINAL>
__global__ __launch_bounds__(256) void stats_kernel(
    const float* __restrict__ beta_v,
    const float* __restrict__ beta_a,
    float lam,
    float* __restrict__ out)
{
    const int warp = (blockIdx.x * blockDim.x + threadIdx.x) >> 5;
    const int lane = threadIdx.x & 31;
    const int b = warp >> 7;
    const int j = warp & 127;

    const float* base = g_part + ((size_t)b * NTc * NOc + j) * RW;
    float acc = 0.f, acc2 = 0.f;
    #pragma unroll 4
    for (int tile = 0; tile < NTc; tile++) {
        const float* row = base + (size_t)tile * (NOc * RW);
        acc += row[lane];
        if (lane < 4) acc2 += row[32 + lane];
    }

    const int d  = lane & 15;
    const int q  = d & 3, pp = (d >> 3) & 1, hd = (d >> 2) & 1;
    const int sl = 8 * pp + 2 * q + hd;
    const float S0  = __shfl_sync(0xffffffffu, acc, 0);
    const float S1d = __shfl_sync(0xffffffffu, acc, 4 + sl);
    const float s2a = __shfl_sync(0xffffffffu, acc, (20 + sl) & 31);
    const float s2b = __shfl_sync(0xffffffffu, acc2, (sl >= 12) ? (sl - 12) : 0);
    const float S2d = (sl < 12) ? s2a : s2b;

    const float Rs = S0 + EPSf;
    const float invRs = 1.f / Rs;
    const float muv = S1d * invRs;
    const float srp = S2d - 2.f * muv * S1d + muv * muv * S0;  // exact expansion
    const float sig = srp * invRs + EPSf;
    const float A   = 1.f / sig;
    const float lg  = logf(sig);
    float logsum = lg;
    #pragma unroll
    for (int off = 8; off; off >>= 1)
        logsum += __shfl_xor_sync(0xffffffffu, logsum, off);
    float muq = muv * muv * A;          // for L' correction
    #pragma unroll
    for (int off = 8; off; off >>= 1)
        muq += __shfl_xor_sync(0xffffffffu, muq, off);

    const float cost = (16.f * beta_v[j] + 0.5f * logsum) * Rs;
    const float aout = 1.f / (1.f + expf(-(lam * (beta_a[j] - cost))));

    if (FINAL) {
        if (lane < 16) out[(size_t)(b * NOc + j) * 16 + d] = muv;
        if (lane == 0) out[(size_t)Bn * NOc * 16 + b * NOc + j] = aout;
    } else {
        float* st = g_statsT + (size_t)b * 33 * NOc;
        if (lane < 16) {
            st[d * NOc + j]        = A;                 // A = 1/sig
            st[(16 + d) * NOc + j] = -2.f * muv * A;    // B = -2mu/sig
        }
        if (lane == 0)
            st[32 * NOc + j] = logf(aout + EPSf) - 0.5f * logsum
                               - 8.f * LOG2PIf - 0.5f * muq;   // L'
    }
}

extern "C" void kernel_launch(void* const* d_in, const int* in_sizes, int n_in,
                              void* d_out, int out_size) {
    const float* pose   = (const float*)d_in[0];
    const float* act    = (const float*)d_in[1];
    const float* W      = (const float*)d_in[2];
    const float* beta_v = (const float*)d_in[3];
    const float* beta_a = (const float*)d_in[4];
    float* out = (float*)d_out;

    dim3 gp(NTc, Bn / 2);                        // 64 x 16 blocks of 128
    const int sgrid = (Bn * NOc * 32) / 256;     // 512 blocks of 256
    const size_t dynX = 2 * TIc * NOc * sizeof(float);   // 32 KB dynamic sX
    const size_t dynU = 2 * TIc * sizeof(float);         // 256 B (uniform act)

    // Raise the dynamic-smem cap for the non-uniform fused kernel
    // (static 24 KB + dynamic 32 KB > 48 KB default). Attribute setter:
    // not a stream op / alloc / sync -> graph-capture safe, idempotent.
    cudaFuncSetAttribute((const void*)fused_kernel<false>,
                         cudaFuncAttributeMaxDynamicSharedMemorySize, (int)dynX);

    wt_kernel<<<NIc, 128>>>(W);                  // pack+transpose W once

    // t=0: uniform R (accumulate only)
    fused_kernel<true><<<gp, 128, dynU>>>(pose, act);
    stats_kernel<false><<<sgrid, 256>>>(beta_v, beta_a, LAM1, out);
    // t=1: logits + in-block softmax (in-place rp) + accumulate
    fused_kernel<false><<<gp, 128, dynX>>>(pose, act);
    stats_kernel<false><<<sgrid, 256>>>(beta_v, beta_a, LAM2, out);
    // t=2
    fused_kernel<false><<<gp, 128, dynX>>>(pose, act);
    stats_kernel<true><<<sgrid, 256>>>(beta_v, beta_a, LAM3, out);
}